// round 9
// baseline (speedup 1.0000x reference)
#include <cuda_runtime.h>
#include <limits.h>

// Problem shape (fixed by setup_inputs): B=256, N=65536, half=32768.
#define NCOL      65536
#define HALF      32768
#define C4ROW     8192               // float4 per half-row
#define BDIM      512
#define CHUNK_F4  512                // float4 per stream per stage
#define NCHUNK    (C4ROW / CHUNK_F4) // 16 stages per row
#define NSTAGE    3
#define STREAM_BYTES (CHUNK_F4 * 16)         // 8192
#define STAGE_BYTES  (STREAM_BYTES * 4)      // 32768
#define SMEM_DYN     (NSTAGE * STAGE_BYTES + 128)
#define MAXB      1024

#define THRESH  0.01f
#define PENALTY 2.0f

__device__ float        g_partials[MAXB];
__device__ unsigned int g_counter = 0;

// ---------------- PTX helpers ----------------
__device__ __forceinline__ unsigned smem_u32(const void* p) {
    unsigned a;
    asm("{ .reg .u64 t; cvta.to.shared.u64 t, %1; cvt.u32.u64 %0, t; }"
        : "=r"(a) : "l"(p));
    return a;
}
__device__ __forceinline__ void mbar_init(unsigned mbar, unsigned count) {
    asm volatile("mbarrier.init.shared.b64 [%0], %1;" :: "r"(mbar), "r"(count) : "memory");
}
__device__ __forceinline__ void mbar_expect_tx(unsigned mbar, unsigned bytes) {
    asm volatile("mbarrier.arrive.expect_tx.shared.b64 _, [%0], %1;"
                 :: "r"(mbar), "r"(bytes) : "memory");
}
__device__ __forceinline__ void mbar_wait(unsigned mbar, unsigned parity) {
    asm volatile(
        "{\n\t"
        ".reg .pred P;\n\t"
        "WAITLP:\n\t"
        "mbarrier.try_wait.parity.acquire.cta.shared::cta.b64 P, [%0], %1, 0x989680;\n\t"
        "@P bra.uni WAITDN;\n\t"
        "bra.uni WAITLP;\n\t"
        "WAITDN:\n\t"
        "}"
        :: "r"(mbar), "r"(parity) : "memory");
}
__device__ __forceinline__ void bulk_g2s(unsigned dst, const void* src,
                                         unsigned bytes, unsigned mbar) {
    asm volatile(
        "cp.async.bulk.shared::cta.global.mbarrier::complete_tx::bytes "
        "[%0], [%1], %2, [%3];"
        :: "r"(dst), "l"(src), "r"(bytes), "r"(mbar) : "memory");
}
__device__ __forceinline__ void fence_async_init() {
    asm volatile("fence.proxy.async.shared::cta;" ::: "memory");
}

__global__ __launch_bounds__(BDIM, 2)
void fused_loss_kernel(const float* __restrict__ pred,
                       const float* __restrict__ lab,
                       float* __restrict__ out,
                       int B)
{
    extern __shared__ float4 sbuf[];   // NSTAGE stages of [4 streams][CHUNK_F4]
    const unsigned mbar0 = smem_u32((char*)sbuf + NSTAGE * STAGE_BYTES);

    const int b = blockIdx.x;
    const size_t row = (size_t)b * NCOL;
    const float* lr = lab  + row;
    const float* li = lab  + row + HALF;
    const float* pr = pred + row;
    const float* pi = pred + row + HALF;

    __shared__ int  s_min_r, s_max_r, s_min_i, s_max_i;
    __shared__ int  s_fr, s_lr, s_fi, s_li;
    __shared__ bool s_is_last;

    const int tid  = threadIdx.x;
    const int lane = tid & 31;
    const int warp = tid >> 5;

    if (tid == 0) {
        s_min_r = INT_MAX; s_max_r = -1;
        s_min_i = INT_MAX; s_max_i = -1;
        #pragma unroll
        for (int s = 0; s < NSTAGE; s++) mbar_init(mbar0 + s * 8, 1);
        fence_async_init();
    }
    __syncthreads();

    // Producer: issue one stage = expect_tx(32KB) + 4 bulk copies (zero regs held).
    auto issue = [&](int c) {
        int bf = c % NSTAGE;
        unsigned mb = mbar0 + bf * 8;
        unsigned d  = smem_u32(sbuf) + bf * STAGE_BYTES;
        const size_t off = (size_t)c * CHUNK_F4 * 4;   // floats
        mbar_expect_tx(mb, STAGE_BYTES);
        bulk_g2s(d                 , lr + off, STREAM_BYTES, mb);
        bulk_g2s(d + STREAM_BYTES  , li + off, STREAM_BYTES, mb);
        bulk_g2s(d + 2*STREAM_BYTES, pr + off, STREAM_BYTES, mb);
        bulk_g2s(d + 3*STREAM_BYTES, pi + off, STREAM_BYTES, mb);
    };

    if (tid == 0) {
        #pragma unroll
        for (int c = 0; c < NSTAGE; c++) issue(c);
    }

    // ============== pipelined consume: 16 stages ==============
    float acc = 0.0f;
    int minr = INT_MAX, maxr = -1;
    int mini = INT_MAX, maxi = -1;

    for (int c = 0; c < NCHUNK; c++) {
        const int bf = c % NSTAGE;
        const unsigned parity = (c / NSTAGE) & 1;
        if (tid == 0) mbar_wait(mbar0 + bf * 8, parity);
        __syncthreads();                    // broadcast "stage ready"

        const float4* st = sbuf + bf * (STAGE_BYTES / 16);
        float4 L  = st[tid];
        float4 Li = st[CHUNK_F4     + tid];
        float4 P  = st[2 * CHUNK_F4 + tid];
        float4 Pi = st[3 * CHUNK_F4 + tid];
        const int c4 = c * CHUNK_F4 + tid;

        float m_r = fmaxf(fmaxf(fabsf(L.x),  fabsf(L.y)),  fmaxf(fabsf(L.z),  fabsf(L.w)));
        float m_i = fmaxf(fmaxf(fabsf(Li.x), fabsf(Li.y)), fmaxf(fabsf(Li.z), fabsf(Li.w)));
        if (m_r > THRESH) { minr = min(minr, c4); maxr = max(maxr, c4); }
        if (m_i > THRESH) { mini = min(mini, c4); maxi = max(maxi, c4); }

        #pragma unroll
        for (int k = 0; k < 4; k++) {
            float lrx = (&L.x)[k],  lix = (&Li.x)[k];
            float prx = (&P.x)[k],  pix = (&Pi.x)[k];
            float dr   = prx - lrx;
            float di   = pix - lix;
            float dint = fmaf(pix, pix, prx * prx) - fmaf(lix, lix, lrx * lrx);
            acc = fmaf(dr, dr, acc);
            acc = fmaf(di, di, acc);
            acc = fmaf(50.0f * dint, dint, acc);
        }

        __syncthreads();                    // all lanes done with this buffer
        if (tid == 0 && c + NSTAGE < NCHUNK) issue(c + NSTAGE);
    }

    // ---- one-time min/max reduction -----------------------------------------
    #pragma unroll
    for (int off = 16; off > 0; off >>= 1) {
        minr = min(minr, __shfl_xor_sync(0xFFFFFFFFu, minr, off));
        maxr = max(maxr, __shfl_xor_sync(0xFFFFFFFFu, maxr, off));
        mini = min(mini, __shfl_xor_sync(0xFFFFFFFFu, mini, off));
        maxi = max(maxi, __shfl_xor_sync(0xFFFFFFFFu, maxi, off));
    }
    if (lane == 0) {
        atomicMin(&s_min_r, minr);
        atomicMax(&s_max_r, maxr);
        atomicMin(&s_min_i, mini);
        atomicMax(&s_max_i, maxi);
    }
    __syncthreads();

    // ---- refine 4-granular bounds to element-exact (thread 0) ---------------
    if (tid == 0) {
        int fr = 0, lrr = HALF - 1, fi = 0, lii = HALF - 1;
        if (s_max_r >= 0) {
            int f = s_min_r * 4;     while (fabsf(lr[f]) <= THRESH) f++;
            int l = s_max_r * 4 + 3; while (fabsf(lr[l]) <= THRESH) l--;
            fr = f; lrr = l;
        }
        if (s_max_i >= 0) {
            int f = s_min_i * 4;     while (fabsf(li[f]) <= THRESH) f++;
            int l = s_max_i * 4 + 3; while (fabsf(li[l]) <= THRESH) l--;
            fi = f; lii = l;
        }
        s_fr = fr; s_lr = lrr; s_fi = fi; s_li = lii;
    }
    __syncthreads();

    // ---- correction: (P-1) * sum of d^2 outside [first,last] (tiny region) --
    {
        const int fr = s_fr, lrr = s_lr, fi = s_fi, lii = s_li;
        float corr = 0.0f;
        for (int j = tid; j < fr; j += BDIM)             { float d = pr[j] - lr[j]; corr = fmaf(d, d, corr); }
        for (int j = lrr + 1 + tid; j < HALF; j += BDIM) { float d = pr[j] - lr[j]; corr = fmaf(d, d, corr); }
        for (int j = tid; j < fi; j += BDIM)             { float d = pi[j] - li[j]; corr = fmaf(d, d, corr); }
        for (int j = lii + 1 + tid; j < HALF; j += BDIM) { float d = pi[j] - li[j]; corr = fmaf(d, d, corr); }
        acc = fmaf(PENALTY - 1.0f, corr, acc);
    }

    // ---- block sum reduction -------------------------------------------------
    __shared__ float s_warp[BDIM / 32];
    #pragma unroll
    for (int off = 16; off > 0; off >>= 1)
        acc += __shfl_xor_sync(0xFFFFFFFFu, acc, off);
    if (lane == 0)
        s_warp[warp] = acc;
    __syncthreads();
    if (tid < 32) {
        float v = (tid < BDIM / 32) ? s_warp[tid] : 0.0f;
        #pragma unroll
        for (int off = 16; off > 0; off >>= 1)
            v += __shfl_xor_sync(0xFFFFFFFFu, v, off);
        if (tid == 0)
            g_partials[b] = v;
    }

    // ---- last CTA folds the per-row partials (self-resetting for graphs) ----
    if (tid == 0) {
        __threadfence();
        unsigned int ticket = atomicAdd(&g_counter, 1u);
        s_is_last = (ticket == (unsigned int)(B - 1));
    }
    __syncthreads();

    if (s_is_last) {
        __threadfence();
        __shared__ float s_fin[256];
        if (tid < 256)
            s_fin[tid] = (tid < B) ? g_partials[tid] : 0.0f;
        __syncthreads();
        #pragma unroll
        for (int st = 128; st > 0; st >>= 1) {
            if (tid < st) s_fin[tid] += s_fin[tid + st];
            __syncthreads();
        }
        if (tid == 0) {
            out[0] = s_fin[0] / ((float)HALF * (float)B);
            g_counter = 0;   // reset for graph replay
        }
    }
}

extern "C" void kernel_launch(void* const* d_in, const int* in_sizes, int n_in,
                              void* d_out, int out_size)
{
    const float* pred = (const float*)d_in[0];
    const float* lab  = (const float*)d_in[1];
    float* out = (float*)d_out;

    const int B = in_sizes[0] / NCOL;   // 256

    cudaFuncSetAttribute(fused_loss_kernel,
                         cudaFuncAttributeMaxDynamicSharedMemorySize, SMEM_DYN);
    fused_loss_kernel<<<B, BDIM, SMEM_DYN>>>(pred, lab, out, B);
}

// round 10
// speedup vs baseline: 1.0409x; 1.0409x over previous
#include <cuda_runtime.h>
#include <limits.h>

// Problem shape (fixed by setup_inputs): B=256, N=65536, half=32768.
#define NCOL    65536
#define HALF    32768
#define C4ROW   8192               // float4 per half-row
#define BDIM    512
#define GRID    296                // 2 CTAs per SM on 148-SM chip, all equal
#define NROWMAX 512

#define THRESH  0.01f
#define PENALTY 2.0f

// Zero-initialized; all mutable state is reset by its last reader each run.
__device__ float    g_cta[GRID];
__device__ float    g_rowcorr[NROWMAX];
__device__ int      g_encf_r[NROWMAX];  // atomicMax of (C4ROW - min_c4); 0 = none
__device__ int      g_encl_r[NROWMAX];  // atomicMax of (max_c4 + 1);     0 = none
__device__ int      g_encf_i[NROWMAX];
__device__ int      g_encl_i[NROWMAX];
__device__ unsigned g_rowcnt[NROWMAX];
__device__ unsigned g_done = 0;

// ---- cache-policy loads (createpolicy + L2::cache_hint, sm_100-legal) ------
__device__ __forceinline__ unsigned long long pol_keep_mk() {
    unsigned long long p;
    asm("createpolicy.fractional.L2::evict_last.b64 %0, 1.0;" : "=l"(p));
    return p;
}
__device__ __forceinline__ unsigned long long pol_stream_mk() {
    unsigned long long p;
    asm("createpolicy.fractional.L2::evict_first.b64 %0, 1.0;" : "=l"(p));
    return p;
}
__device__ __forceinline__ float4 ld_pol(const float4* p, unsigned long long pol) {
    float4 v;
    asm volatile("ld.global.nc.L2::cache_hint.v4.f32 {%0,%1,%2,%3}, [%4], %5;"
                 : "=f"(v.x), "=f"(v.y), "=f"(v.z), "=f"(v.w)
                 : "l"(p), "l"(pol));
    return v;
}

__global__ __launch_bounds__(BDIM, 2)
void fused_loss_kernel(const float* __restrict__ pred,
                       const float* __restrict__ lab,
                       float* __restrict__ out,
                       int B)
{
    const long long TOT = (long long)B * C4ROW;     // global c4 columns
    const int c  = blockIdx.x;
    const int x0 = (int)(( (long long)c      * TOT) / GRID);   // global c4 range
    const int x1 = (int)(( (long long)(c+1) * TOT) / GRID);
    const int r0 = x0 / C4ROW;
    const int r1 = (x1 - 1) / C4ROW;

    const int tid  = threadIdx.x;
    const int lane = tid & 31;
    const int warp = tid >> 5;

    const unsigned long long PK = pol_keep_mk();
    const unsigned long long PS = pol_stream_mk();

    __shared__ int   s_minr, s_maxr, s_mini, s_maxi;
    __shared__ int   s_fr, s_lr, s_fi, s_li;
    __shared__ int   s_docorr;
    __shared__ float s_warp[BDIM / 32];
    __shared__ int   s_lastall;

    // =================== PHASE 1: label min/max per row-segment ==============
    for (int r = r0; r <= r1; r++) {
        const int a = max(x0, r * C4ROW)       - r * C4ROW;   // c4 within half
        const int e = min(x1, (r + 1) * C4ROW) - r * C4ROW;
        const float4* Lr4 = (const float4*)(lab + (size_t)r * NCOL);
        const float4* Li4 = Lr4 + (C4ROW / 1);                // imag half offset in f4
        // note: imag half starts HALF floats = C4ROW float4 after real
        if (tid == 0) { s_minr = INT_MAX; s_maxr = -1; s_mini = INT_MAX; s_maxi = -1; }
        __syncthreads();

        int minr = INT_MAX, maxr = -1, mini = INT_MAX, maxi = -1;
        #pragma unroll 4
        for (int j4 = a + tid; j4 < e; j4 += BDIM) {
            float4 L  = ld_pol(Lr4 + j4, PK);
            float4 Li = ld_pol(Li4 + j4, PK);
            float m_r = fmaxf(fmaxf(fabsf(L.x),  fabsf(L.y)),  fmaxf(fabsf(L.z),  fabsf(L.w)));
            float m_i = fmaxf(fmaxf(fabsf(Li.x), fabsf(Li.y)), fmaxf(fabsf(Li.z), fabsf(Li.w)));
            if (m_r > THRESH) { minr = min(minr, j4); maxr = max(maxr, j4); }
            if (m_i > THRESH) { mini = min(mini, j4); maxi = max(maxi, j4); }
        }
        #pragma unroll
        for (int off = 16; off > 0; off >>= 1) {
            minr = min(minr, __shfl_xor_sync(0xFFFFFFFFu, minr, off));
            maxr = max(maxr, __shfl_xor_sync(0xFFFFFFFFu, maxr, off));
            mini = min(mini, __shfl_xor_sync(0xFFFFFFFFu, mini, off));
            maxi = max(maxi, __shfl_xor_sync(0xFFFFFFFFu, maxi, off));
        }
        if (lane == 0) {
            atomicMin(&s_minr, minr);
            atomicMax(&s_maxr, maxr);
            atomicMin(&s_mini, mini);
            atomicMax(&s_maxi, maxi);
        }
        __syncthreads();

        if (tid == 0) {
            if (s_maxr >= 0) {
                atomicMax(&g_encf_r[r], C4ROW - s_minr);
                atomicMax(&g_encl_r[r], s_maxr + 1);
            }
            if (s_maxi >= 0) {
                atomicMax(&g_encf_i[r], C4ROW - s_mini);
                atomicMax(&g_encl_i[r], s_maxi + 1);
            }
            __threadfence();
            // expected arrivals = #CTAs whose range intersects row r
            long long lo = (long long)r * C4ROW, hi = lo + C4ROW - 1;
            int cfirst = (int)(((lo + 1) * GRID - 1) / TOT);
            int clast  = (int)(((hi + 1) * GRID - 1) / TOT);
            unsigned tk = atomicAdd(&g_rowcnt[r], 1u);
            s_docorr = (tk == (unsigned)(clast - cfirst));
        }
        __syncthreads();

        // -------- last arriver computes the row's penalty correction --------
        if (s_docorr) {
            if (tid == 0) {
                __threadfence();                       // acquire all flushes
                int efr = g_encf_r[r], elr = g_encl_r[r];
                int efi = g_encf_i[r], eli = g_encl_i[r];
                const float* Lr = lab + (size_t)r * NCOL;
                const float* Lj = Lr + HALF;
                int fr = 0, lrr = HALF - 1, fi = 0, lii = HALF - 1;
                if (elr > 0) {
                    fr  = (C4ROW - efr) * 4; while (fabsf(Lr[fr])  <= THRESH) fr++;
                    lrr = (elr - 1) * 4 + 3; while (fabsf(Lr[lrr]) <= THRESH) lrr--;
                }
                if (eli > 0) {
                    fi  = (C4ROW - efi) * 4; while (fabsf(Lj[fi])  <= THRESH) fi++;
                    lii = (eli - 1) * 4 + 3; while (fabsf(Lj[lii]) <= THRESH) lii--;
                }
                s_fr = fr; s_lr = lrr; s_fi = fi; s_li = lii;
                g_encf_r[r] = 0; g_encl_r[r] = 0;      // reset for replay
                g_encf_i[r] = 0; g_encl_i[r] = 0;
                g_rowcnt[r] = 0;
            }
            __syncthreads();
            const float* Lr = lab  + (size_t)r * NCOL;
            const float* Pr = pred + (size_t)r * NCOL;
            const float* Lj = Lr + HALF;
            const float* Pj = Pr + HALF;
            const int fr = s_fr, lrr = s_lr, fi = s_fi, lii = s_li;
            float corr = 0.0f;                          // outside region: tiny
            for (int j = tid; j < fr; j += BDIM)             { float d = Pr[j] - Lr[j]; corr = fmaf(d, d, corr); }
            for (int j = lrr + 1 + tid; j < HALF; j += BDIM) { float d = Pr[j] - Lr[j]; corr = fmaf(d, d, corr); }
            for (int j = tid; j < fi; j += BDIM)             { float d = Pj[j] - Lj[j]; corr = fmaf(d, d, corr); }
            for (int j = lii + 1 + tid; j < HALF; j += BDIM) { float d = Pj[j] - Lj[j]; corr = fmaf(d, d, corr); }
            #pragma unroll
            for (int off = 16; off > 0; off >>= 1)
                corr += __shfl_xor_sync(0xFFFFFFFFu, corr, off);
            if (lane == 0) s_warp[warp] = corr;
            __syncthreads();
            if (tid == 0) {
                float cs = 0.0f;
                #pragma unroll
                for (int w = 0; w < BDIM / 32; w++) cs += s_warp[w];
                g_rowcorr[r] = (PENALTY - 1.0f) * cs;   // row-deterministic value
            }
            __syncthreads();
        }
    }

    // =================== PHASE 2: unweighted base loss ========================
    // pred from DRAM (stream), label re-read from L2 (kept by phase 1).
    float acc = 0.0f;
    for (int r = r0; r <= r1; r++) {
        const int a = max(x0, r * C4ROW)       - r * C4ROW;
        const int e = min(x1, (r + 1) * C4ROW) - r * C4ROW;
        const float4* Lr4 = (const float4*)(lab  + (size_t)r * NCOL);
        const float4* Li4 = Lr4 + C4ROW;
        const float4* Pr4 = (const float4*)(pred + (size_t)r * NCOL);
        const float4* Pi4 = Pr4 + C4ROW;

        #pragma unroll 2
        for (int j4 = a + tid; j4 < e; j4 += BDIM) {
            float4 L  = ld_pol(Lr4 + j4, PS);
            float4 Li = ld_pol(Li4 + j4, PS);
            float4 P  = ld_pol(Pr4 + j4, PS);
            float4 Pi = ld_pol(Pi4 + j4, PS);
            #pragma unroll
            for (int k = 0; k < 4; k++) {
                float lrx = (&L.x)[k],  lix = (&Li.x)[k];
                float prx = (&P.x)[k],  pix = (&Pi.x)[k];
                float dr   = prx - lrx;
                float di   = pix - lix;
                float dint = fmaf(pix, pix, prx * prx) - fmaf(lix, lix, lrx * lrx);
                acc = fmaf(dr, dr, acc);
                acc = fmaf(di, di, acc);
                acc = fmaf(50.0f * dint, dint, acc);
            }
        }
    }

    // ---- CTA fold ------------------------------------------------------------
    #pragma unroll
    for (int off = 16; off > 0; off >>= 1)
        acc += __shfl_xor_sync(0xFFFFFFFFu, acc, off);
    if (lane == 0) s_warp[warp] = acc;
    __syncthreads();
    if (tid == 0) {
        float a = 0.0f;
        #pragma unroll
        for (int w = 0; w < BDIM / 32; w++) a += s_warp[w];
        g_cta[c] = a;
        __threadfence();
        unsigned t = atomicAdd(&g_done, 1u);
        s_lastall = (t == (unsigned)(GRID - 1));
    }
    __syncthreads();
    if (!s_lastall) return;

    // ---- final fold (fixed order -> deterministic) ---------------------------
    __threadfence();
    __shared__ float s_fin[BDIM];
    float v = 0.0f;
    for (int i = tid; i < GRID; i += BDIM) v += g_cta[i];
    for (int i = tid; i < B;    i += BDIM) v += g_rowcorr[i];
    s_fin[tid] = v;
    __syncthreads();
    #pragma unroll
    for (int st = BDIM / 2; st > 0; st >>= 1) {
        if (tid < st) s_fin[tid] += s_fin[tid + st];
        __syncthreads();
    }
    if (tid == 0) {
        out[0] = s_fin[0] / ((float)HALF * (float)B);
        g_done = 0;   // reset for graph replay
    }
}

extern "C" void kernel_launch(void* const* d_in, const int* in_sizes, int n_in,
                              void* d_out, int out_size)
{
    const float* pred = (const float*)d_in[0];
    const float* lab  = (const float*)d_in[1];
    float* out = (float*)d_out;

    const int B = in_sizes[0] / NCOL;   // 256

    fused_loss_kernel<<<GRID, BDIM>>>(pred, lab, out, B);
}

// round 11
// speedup vs baseline: 1.2545x; 1.2052x over previous
#include <cuda_runtime.h>
#include <limits.h>

// Problem shape (fixed by setup_inputs): B=256, N=65536, half=32768.
#define NCOL   65536
#define HALF   32768
#define C4ROW  8192              // float4 per half-row
#define C4FULL 16384             // float4 per full row
#define BDIM   512
#define MAXB   1024

#define THRESH  0.01f
#define PENALTY 2.0f

__device__ float        g_partials[MAXB];
__device__ unsigned int g_counter = 0;

// ---- cache-policy loads (createpolicy + L2::cache_hint form) ---------------
__device__ __forceinline__ unsigned long long mk_policy_evict_last() {
    unsigned long long pol;
    asm("createpolicy.fractional.L2::evict_last.b64 %0, 1.0;" : "=l"(pol));
    return pol;
}
__device__ __forceinline__ unsigned long long mk_policy_evict_first() {
    unsigned long long pol;
    asm("createpolicy.fractional.L2::evict_first.b64 %0, 1.0;" : "=l"(pol));
    return pol;
}
__device__ __forceinline__ float4 ld_pol(const float4* p, unsigned long long pol) {
    float4 v;
    asm volatile("ld.global.nc.L2::cache_hint.v4.f32 {%0,%1,%2,%3}, [%4], %5;"
                 : "=f"(v.x), "=f"(v.y), "=f"(v.z), "=f"(v.w)
                 : "l"(p), "l"(pol));
    return v;
}

__global__ __launch_bounds__(BDIM, 2)
void fused_loss_kernel(const float* __restrict__ pred,
                       const float* __restrict__ lab,
                       float* __restrict__ out,
                       int B)
{
    const int b = blockIdx.x;
    const size_t row = (size_t)b * NCOL;
    const float4* __restrict__ lrow4 = (const float4*)(lab + row);   // full row
    const float4* __restrict__ lr4   = lrow4;
    const float4* __restrict__ li4   = lrow4 + C4ROW;
    const float4* __restrict__ pr4   = (const float4*)(pred + row);
    const float4* __restrict__ pi4   = (const float4*)(pred + row) + C4ROW;

    const unsigned long long pol_keep   = mk_policy_evict_last();
    const unsigned long long pol_stream = mk_policy_evict_first();

    __shared__ int  s_min_r, s_max_r, s_min_i, s_max_i;
    __shared__ bool s_is_last;
    if (threadIdx.x == 0) {
        s_min_r = INT_MAX; s_max_r = -1;
        s_min_i = INT_MAX; s_max_i = -1;
    }
    __syncthreads();

    const int lane = threadIdx.x & 31;
    const int warp = threadIdx.x >> 5;

    // ==== Phase 1: ONE contiguous stream over the full 256KB label row =======
    // it in [0,16) covers the real half, [16,32) the imag half: the half is a
    // compile-time property of each unrolled iteration -> scalar tracking only.
    int tmin_r = INT_MAX, tmax_r = -1;
    int tmin_i = INT_MAX, tmax_i = -1;

    #pragma unroll 8
    for (int it = 0; it < 16; it++) {                    // real half
        int c4 = threadIdx.x + it * BDIM;
        float4 v = ld_pol(lr4 + c4, pol_keep);
        float m = fmaxf(fmaxf(fabsf(v.x), fabsf(v.y)), fmaxf(fabsf(v.z), fabsf(v.w)));
        if (m > THRESH) { tmin_r = min(tmin_r, c4); tmax_r = max(tmax_r, c4); }
    }
    #pragma unroll 8
    for (int it = 0; it < 16; it++) {                    // imag half
        int c4 = threadIdx.x + it * BDIM;
        float4 v = ld_pol(li4 + c4, pol_keep);
        float m = fmaxf(fmaxf(fabsf(v.x), fabsf(v.y)), fmaxf(fabsf(v.z), fabsf(v.w)));
        if (m > THRESH) { tmin_i = min(tmin_i, c4); tmax_i = max(tmax_i, c4); }
    }

    #pragma unroll
    for (int off = 16; off > 0; off >>= 1) {
        tmin_r = min(tmin_r, __shfl_xor_sync(0xFFFFFFFFu, tmin_r, off));
        tmax_r = max(tmax_r, __shfl_xor_sync(0xFFFFFFFFu, tmax_r, off));
        tmin_i = min(tmin_i, __shfl_xor_sync(0xFFFFFFFFu, tmin_i, off));
        tmax_i = max(tmax_i, __shfl_xor_sync(0xFFFFFFFFu, tmax_i, off));
    }
    if (lane == 0) {
        atomicMin(&s_min_r, tmin_r);
        atomicMax(&s_max_r, tmax_r);
        atomicMin(&s_min_i, tmin_i);
        atomicMax(&s_max_i, tmax_i);
    }
    __syncthreads();

    // refine 4-granular bounds to element-exact (matches reference semantics)
    __shared__ int s_b[4];
    if (threadIdx.x == 0) {
        const float* Lr = lab + row;
        const float* Lj = lab + row + HALF;
        int fr = 0, lrr = HALF - 1, fi = 0, lii = HALF - 1;
        if (s_max_r >= 0) {
            int f = s_min_r * 4;     while (fabsf(Lr[f]) <= THRESH) f++;
            int l = s_max_r * 4 + 3; while (fabsf(Lr[l]) <= THRESH) l--;
            fr = f; lrr = l;
        }
        if (s_max_i >= 0) {
            int f = s_min_i * 4;     while (fabsf(Lj[f]) <= THRESH) f++;
            int l = s_max_i * 4 + 3; while (fabsf(Lj[l]) <= THRESH) l--;
            fi = f; lii = l;
        }
        s_b[0] = fr; s_b[1] = lrr; s_b[2] = fi; s_b[3] = lii;
    }
    __syncthreads();
    const int fr = s_b[0], lr = s_b[1], fi = s_b[2], li = s_b[3];

    // ==== Phase 2: weighted MSE; pred from DRAM, label from L2 ===============
    // Three independent accumulator chains (breaks the 12-FMA serial chain).
    float accR = 0.0f, accI = 0.0f, accQ = 0.0f;

    #pragma unroll 2
    for (int it = 0; it < 16; it++) {
        int c4 = threadIdx.x + it * BDIM;
        float4 lrv = ld_pol(lr4 + c4, pol_stream);
        float4 liv = ld_pol(li4 + c4, pol_stream);
        float4 prv = ld_pol(pr4 + c4, pol_stream);
        float4 piv = ld_pol(pi4 + c4, pol_stream);
        int base = c4 * 4;

        #pragma unroll
        for (int k = 0; k < 4; k++) {
            float lrx = (&lrv.x)[k];
            float lix = (&liv.x)[k];
            float prx = (&prv.x)[k];
            float pix = (&piv.x)[k];
            int   j   = base + k;

            float dr   = prx - lrx;
            float di   = pix - lix;
            float dint = fmaf(pix, pix, prx * prx) - fmaf(lix, lix, lrx * lrx);

            float wr = (j < fr || j > lr) ? PENALTY : 1.0f;
            float wi = (j < fi || j > li) ? PENALTY : 1.0f;

            accR = fmaf(wr * dr, dr, accR);
            accI = fmaf(wi * di, di, accI);
            accQ = fmaf(dint, dint, accQ);
        }
    }
    float acc = accR + accI + 50.0f * accQ;

    // ---- block sum reduction -------------------------------------------------
    __shared__ float s_warp[BDIM / 32];
    #pragma unroll
    for (int off = 16; off > 0; off >>= 1)
        acc += __shfl_xor_sync(0xFFFFFFFFu, acc, off);
    if (lane == 0)
        s_warp[warp] = acc;
    __syncthreads();
    if (threadIdx.x < 32) {
        float v = (threadIdx.x < BDIM / 32) ? s_warp[threadIdx.x] : 0.0f;
        #pragma unroll
        for (int off = 16; off > 0; off >>= 1)
            v += __shfl_xor_sync(0xFFFFFFFFu, v, off);
        if (threadIdx.x == 0)
            g_partials[b] = v;
    }

    // ---- last CTA folds the per-row partials (self-resetting for graphs) ----
    if (threadIdx.x == 0) {
        __threadfence();
        unsigned int ticket = atomicAdd(&g_counter, 1u);
        s_is_last = (ticket == (unsigned int)(B - 1));
    }
    __syncthreads();

    if (s_is_last) {
        __threadfence();
        __shared__ float s_fin[256];
        if (threadIdx.x < 256)
            s_fin[threadIdx.x] = (threadIdx.x < B) ? g_partials[threadIdx.x] : 0.0f;
        __syncthreads();
        #pragma unroll
        for (int st = 128; st > 0; st >>= 1) {
            if (threadIdx.x < st) s_fin[threadIdx.x] += s_fin[threadIdx.x + st];
            __syncthreads();
        }
        if (threadIdx.x == 0) {
            out[0] = s_fin[0] / ((float)HALF * (float)B);
            g_counter = 0;   // reset for graph replay
        }
    }
}

extern "C" void kernel_launch(void* const* d_in, const int* in_sizes, int n_in,
                              void* d_out, int out_size)
{
    const float* pred = (const float*)d_in[0];
    const float* lab  = (const float*)d_in[1];
    float* out = (float*)d_out;

    const int B = in_sizes[0] / NCOL;   // 256

    fused_loss_kernel<<<B, BDIM>>>(pred, lab, out, B);
}